// round 1
// baseline (speedup 1.0000x reference)
#include <cuda_runtime.h>
#include <math.h>
#include <stdint.h>

// Problem constants
#define BATCH 8
#define SEQ_T 1024
#define SEQ_TP 64
#define CH 1024
#define NHEAD 16
#define HDIM 64
#define C3 (3 * CH)

// Scratch (device globals: allocation-free rule)
__device__ float g_qkv[BATCH * SEQ_T * C3];    // (8192, 3072)
__device__ float g_pqkv[BATCH * SEQ_TP * C3];  // (512, 3072)
__device__ float g_y[BATCH * SEQ_T * CH];      // (8192, 1024)

// ---------------------------------------------------------------------------
// SGEMM: C[M,N] = A[M,K] @ B[K,N] + bias[N]   (all row-major, fp32)
// 128x128 block tile, BK=8, 256 threads, 8x8 per-thread microtile.
// Dims assumed divisible (they are for all three calls).
// ---------------------------------------------------------------------------
__global__ __launch_bounds__(256, 2)
void sgemm_bias_kernel(const float* __restrict__ A,
                       const float* __restrict__ Bm,
                       const float* __restrict__ bias,
                       float* __restrict__ Cm,
                       int M, int N, int K) {
    __shared__ float As[8][128];
    __shared__ float Bs[8][128];

    const int tid = threadIdx.x;
    const int tx = tid & 15;       // 0..15
    const int ty = tid >> 4;       // 0..15
    const int row0 = blockIdx.y * 128;
    const int col0 = blockIdx.x * 128;

    // Global load assignments
    const int arow = tid >> 1;            // 0..127
    const int acol = (tid & 1) * 4;       // 0 or 4
    const int brow = tid >> 5;            // 0..7
    const int bcol = (tid & 31) * 4;      // 0..124

    const float* Aptr = A + (size_t)(row0 + arow) * K + acol;
    const float* Bptr = Bm + (size_t)brow * N + col0 + bcol;

    float acc[8][8];
#pragma unroll
    for (int i = 0; i < 8; i++)
#pragma unroll
        for (int j = 0; j < 8; j++) acc[i][j] = 0.0f;

    for (int k0 = 0; k0 < K; k0 += 8) {
        float4 av = *(const float4*)(Aptr + k0);
        float4 bv = *(const float4*)(Bptr + (size_t)k0 * N);
        As[acol + 0][arow] = av.x;
        As[acol + 1][arow] = av.y;
        As[acol + 2][arow] = av.z;
        As[acol + 3][arow] = av.w;
        *(float4*)&Bs[brow][bcol] = bv;
        __syncthreads();

#pragma unroll
        for (int k = 0; k < 8; k++) {
            float a[8], b[8];
            float4 a0 = *(const float4*)&As[k][ty * 4];
            float4 a1 = *(const float4*)&As[k][64 + ty * 4];
            float4 b0 = *(const float4*)&Bs[k][tx * 4];
            float4 b1 = *(const float4*)&Bs[k][64 + tx * 4];
            a[0] = a0.x; a[1] = a0.y; a[2] = a0.z; a[3] = a0.w;
            a[4] = a1.x; a[5] = a1.y; a[6] = a1.z; a[7] = a1.w;
            b[0] = b0.x; b[1] = b0.y; b[2] = b0.z; b[3] = b0.w;
            b[4] = b1.x; b[5] = b1.y; b[6] = b1.z; b[7] = b1.w;
#pragma unroll
            for (int i = 0; i < 8; i++)
#pragma unroll
                for (int j = 0; j < 8; j++) acc[i][j] += a[i] * b[j];
        }
        __syncthreads();
    }

    // Epilogue with bias, vectorized stores
#pragma unroll
    for (int ih = 0; ih < 2; ih++) {
#pragma unroll
        for (int i = 0; i < 4; i++) {
            int r = row0 + ih * 64 + ty * 4 + i;
#pragma unroll
            for (int jh = 0; jh < 2; jh++) {
                int c = col0 + jh * 64 + tx * 4;
                float4 bvv = *(const float4*)(bias + c);
                float4 o;
                o.x = acc[ih * 4 + i][jh * 4 + 0] + bvv.x;
                o.y = acc[ih * 4 + i][jh * 4 + 1] + bvv.y;
                o.z = acc[ih * 4 + i][jh * 4 + 2] + bvv.z;
                o.w = acc[ih * 4 + i][jh * 4 + 3] + bvv.w;
                *(float4*)(Cm + (size_t)r * N + c) = o;
            }
        }
    }
}

// ---------------------------------------------------------------------------
// Attention: for each (b,h), compute
//   y = softmax(mask(Q K^T * s)) @ V + softmax(mask_p(Q Kp^T * s)) @ Vp
// Flash-style online softmax, run twice (two independent softmaxes), summed.
// Block: 256 threads (16x16), each thread owns a 4x4 of the 64x64 tile.
// Grid: (B*NHEAD, T/64).
// Dynamic smem: Qs[64][65] + KVs[64][65] + Ps[64][65] = 49920 bytes.
// ---------------------------------------------------------------------------
__global__ __launch_bounds__(256, 2)
void attn_kernel(const float* __restrict__ qkv,
                 const float* __restrict__ pqkv,
                 float* __restrict__ y) {
    extern __shared__ float sm[];
    float (*Qs)[65]  = (float(*)[65])sm;
    float (*KVs)[65] = (float(*)[65])(sm + 64 * 65);
    float (*Ps)[65]  = (float(*)[65])(sm + 2 * 64 * 65);

    const int bh = blockIdx.x;
    const int b = bh / NHEAD;
    const int h = bh % NHEAD;
    const int qt = blockIdx.y;
    const int tid = threadIdx.x;
    const int tx = tid & 15;
    const int ty = tid >> 4;
    const float scale = 0.125f;  // 1/sqrt(64)

    // Load Q tile (64 rows x 64 cols) from qkv
    const float* qbase = qkv + (size_t)(b * SEQ_T + qt * 64) * C3 + h * HDIM;
#pragma unroll
    for (int i = 0; i < 4; i++) {
        int lin = tid + i * 256;
        int r = lin >> 4;
        int c4 = (lin & 15) * 4;
        float4 v = *(const float4*)(qbase + (size_t)r * C3 + c4);
        Qs[r][c4] = v.x; Qs[r][c4 + 1] = v.y; Qs[r][c4 + 2] = v.z; Qs[r][c4 + 3] = v.w;
    }

    float out[4][4];
#pragma unroll
    for (int r = 0; r < 4; r++)
#pragma unroll
        for (int c = 0; c < 4; c++) out[r][c] = 0.0f;

    // pass 0: main causal attention over T keys; pass 1: prefix attention over Tp keys
    for (int pass = 0; pass < 2; pass++) {
        float m[4], l[4], o[4][4];
#pragma unroll
        for (int r = 0; r < 4; r++) {
            m[r] = -1e30f; l[r] = 0.0f;
#pragma unroll
            for (int c = 0; c < 4; c++) o[r][c] = 0.0f;
        }
        const int ntiles = (pass == 0) ? (qt + 1) : 1;
        const float* src = (pass == 0) ? qkv : pqkv;
        const int rowbase = (pass == 0) ? (b * SEQ_T) : (b * SEQ_TP);

        for (int kt = 0; kt < ntiles; kt++) {
            __syncthreads();  // previous-iteration V reads / Q load done
            // Load K tile
            const float* kbase = src + (size_t)(rowbase + kt * 64) * C3 + CH + h * HDIM;
#pragma unroll
            for (int i = 0; i < 4; i++) {
                int lin = tid + i * 256;
                int r = lin >> 4;
                int c4 = (lin & 15) * 4;
                float4 v = *(const float4*)(kbase + (size_t)r * C3 + c4);
                KVs[r][c4] = v.x; KVs[r][c4 + 1] = v.y; KVs[r][c4 + 2] = v.z; KVs[r][c4 + 3] = v.w;
            }
            __syncthreads();

            // S = Q K^T (4x4 per thread)
            float S[4][4];
#pragma unroll
            for (int r = 0; r < 4; r++)
#pragma unroll
                for (int c = 0; c < 4; c++) S[r][c] = 0.0f;
#pragma unroll 8
            for (int k = 0; k < 64; k++) {
                float a[4], bb[4];
#pragma unroll
                for (int r = 0; r < 4; r++) a[r] = Qs[ty * 4 + r][k];
#pragma unroll
                for (int c = 0; c < 4; c++) bb[c] = KVs[tx * 4 + c][k];
#pragma unroll
                for (int r = 0; r < 4; r++)
#pragma unroll
                    for (int c = 0; c < 4; c++) S[r][c] += a[r] * bb[c];
            }

            // scale + causal mask
            const bool need_mask = (pass == 0) ? (kt == qt) : (qt == 0);
            const int qg0 = qt * 64 + ty * 4;
            const int kg0 = kt * 64 + tx * 4;
#pragma unroll
            for (int r = 0; r < 4; r++)
#pragma unroll
                for (int c = 0; c < 4; c++) {
                    float s = S[r][c] * scale;
                    if (need_mask && (kg0 + c > qg0 + r)) s = -1e30f;
                    S[r][c] = s;
                }

            // online softmax update
#pragma unroll
            for (int r = 0; r < 4; r++) {
                float mx = fmaxf(fmaxf(S[r][0], S[r][1]), fmaxf(S[r][2], S[r][3]));
#pragma unroll
                for (int off = 8; off >= 1; off >>= 1)
                    mx = fmaxf(mx, __shfl_xor_sync(0xffffffffu, mx, off));
                float mnew = fmaxf(m[r], mx);
                float alpha = __expf(m[r] - mnew);
                m[r] = mnew;
                float rs = 0.0f;
#pragma unroll
                for (int c = 0; c < 4; c++) {
                    float p = __expf(S[r][c] - mnew);
                    S[r][c] = p;
                    rs += p;
                }
#pragma unroll
                for (int off = 8; off >= 1; off >>= 1)
                    rs += __shfl_xor_sync(0xffffffffu, rs, off);
                l[r] = l[r] * alpha + rs;
#pragma unroll
                for (int c = 0; c < 4; c++) o[r][c] *= alpha;
            }

            // Stage P to smem
#pragma unroll
            for (int r = 0; r < 4; r++)
#pragma unroll
                for (int c = 0; c < 4; c++) Ps[ty * 4 + r][tx * 4 + c] = S[r][c];
            __syncthreads();

            // Load V tile over K tile
            const float* vbase = kbase + CH;
#pragma unroll
            for (int i = 0; i < 4; i++) {
                int lin = tid + i * 256;
                int r = lin >> 4;
                int c4 = (lin & 15) * 4;
                float4 v = *(const float4*)(vbase + (size_t)r * C3 + c4);
                KVs[r][c4] = v.x; KVs[r][c4 + 1] = v.y; KVs[r][c4 + 2] = v.z; KVs[r][c4 + 3] = v.w;
            }
            __syncthreads();

            // o += P @ V
#pragma unroll 8
            for (int k = 0; k < 64; k++) {
                float p[4], vv[4];
#pragma unroll
                for (int r = 0; r < 4; r++) p[r] = Ps[ty * 4 + r][k];
#pragma unroll
                for (int c = 0; c < 4; c++) vv[c] = KVs[k][tx * 4 + c];
#pragma unroll
                for (int r = 0; r < 4; r++)
#pragma unroll
                    for (int c = 0; c < 4; c++) o[r][c] += p[r] * vv[c];
            }
        }

        // normalize and accumulate into final output
#pragma unroll
        for (int r = 0; r < 4; r++) {
            float inv = 1.0f / l[r];
#pragma unroll
            for (int c = 0; c < 4; c++) out[r][c] += o[r][c] * inv;
        }
    }

    // Write y (B*T, C) at head offset
#pragma unroll
    for (int r = 0; r < 4; r++) {
        int qg = qt * 64 + ty * 4 + r;
        float* yp = y + (size_t)(b * SEQ_T + qg) * CH + h * HDIM + tx * 4;
        float4 o4;
        o4.x = out[r][0]; o4.y = out[r][1]; o4.z = out[r][2]; o4.w = out[r][3];
        *(float4*)yp = o4;
    }
}

// ---------------------------------------------------------------------------
// Launch
// ---------------------------------------------------------------------------
extern "C" void kernel_launch(void* const* d_in, const int* in_sizes, int n_in,
                              void* d_out, int out_size) {
    const float* x        = (const float*)d_in[0];
    const float* prefix   = (const float*)d_in[1];
    const float* w_attn   = (const float*)d_in[2];
    const float* b_attn   = (const float*)d_in[3];
    const float* w_prefix = (const float*)d_in[4];
    const float* b_prefix = (const float*)d_in[5];
    const float* w_proj   = (const float*)d_in[6];
    const float* b_proj   = (const float*)d_in[7];
    float* out = (float*)d_out;

    float *qkv_ptr, *pqkv_ptr, *y_ptr;
    cudaGetSymbolAddress((void**)&qkv_ptr, g_qkv);
    cudaGetSymbolAddress((void**)&pqkv_ptr, g_pqkv);
    cudaGetSymbolAddress((void**)&y_ptr, g_y);

    const int smem_attn = 3 * 64 * 65 * sizeof(float);  // 49920
    cudaFuncSetAttribute(attn_kernel, cudaFuncAttributeMaxDynamicSharedMemorySize, smem_attn);

    // 1) qkv = x @ w_attn + b_attn : (8192,1024)x(1024,3072)
    {
        dim3 grid(C3 / 128, (BATCH * SEQ_T) / 128);
        sgemm_bias_kernel<<<grid, 256>>>(x, w_attn, b_attn, qkv_ptr,
                                         BATCH * SEQ_T, C3, CH);
    }
    // 2) pqkv = prefix @ w_prefix + b_prefix : (512,1024)x(1024,3072)
    {
        dim3 grid(C3 / 128, (BATCH * SEQ_TP) / 128);
        sgemm_bias_kernel<<<grid, 256>>>(prefix, w_prefix, b_prefix, pqkv_ptr,
                                         BATCH * SEQ_TP, C3, CH);
    }
    // 3) attention -> y
    {
        dim3 grid(BATCH * NHEAD, SEQ_T / 64);
        attn_kernel<<<grid, 256, smem_attn>>>(qkv_ptr, pqkv_ptr, y_ptr);
    }
    // 4) out = y @ w_proj + b_proj : (8192,1024)x(1024,1024)
    {
        dim3 grid(CH / 128, (BATCH * SEQ_T) / 128);
        sgemm_bias_kernel<<<grid, 256>>>(y_ptr, w_proj, b_proj, out,
                                         BATCH * SEQ_T, CH, CH);
    }
}

// round 3
// speedup vs baseline: 1.4976x; 1.4976x over previous
#include <cuda_runtime.h>
#include <math.h>
#include <stdint.h>

// Problem constants
#define BATCH 8
#define SEQ_T 1024
#define SEQ_TP 64
#define CH 1024
#define NHEAD 16
#define HDIM 64
#define C3 (3 * CH)

// Scratch (device globals: allocation-free rule)
__device__ float g_qkv[BATCH * SEQ_T * C3];    // (8192, 3072)
__device__ float g_pqkv[BATCH * SEQ_TP * C3];  // (512, 3072)
__device__ float g_y[BATCH * SEQ_T * CH];      // (8192, 1024)

// ===========================================================================
// tf32 helpers (compute_80+ features only — no 'a'-gated instructions)
// ===========================================================================
__device__ __forceinline__ uint32_t f2tf32(float f) {
    uint32_t r;
    asm("cvt.rna.tf32.f32 %0, %1;" : "=r"(r) : "f"(f));
    return r;
}

__device__ __forceinline__ void mma_tf32(float* d, const uint32_t* a, const uint32_t* b) {
    asm volatile(
        "mma.sync.aligned.m16n8k8.row.col.f32.tf32.tf32.f32 "
        "{%0,%1,%2,%3}, {%4,%5,%6,%7}, {%8,%9}, {%0,%1,%2,%3};"
        : "+f"(d[0]), "+f"(d[1]), "+f"(d[2]), "+f"(d[3])
        : "r"(a[0]), "r"(a[1]), "r"(a[2]), "r"(a[3]), "r"(b[0]), "r"(b[1]));
}

// ===========================================================================
// tf32 tensor-core GEMM: C[M,N] = A[M,K] @ B[K,N] + bias[N], fp32 in/out.
// Block tile 128x128, BK=32, 256 threads (8 warps as 2x4, warp tile 64x32).
// Double-buffered smem, register-prefetch pipeline.
// Smem (uint32 units): As[2][128][36] (m-major, pad->conflict-free frags),
//                      Bs[2][32][136] (k-major, pad->conflict-free frags).
// ===========================================================================
#define GA_PAD 36
#define GB_PAD 136
#define AS_BUF (128 * GA_PAD)           // 4608 u32
#define BS_BUF (32 * GB_PAD)            // 4352 u32
#define GEMM_SMEM ((2 * AS_BUF + 2 * BS_BUF) * 4)  // 71680 bytes

__global__ __launch_bounds__(256, 1)
void gemm_tf32_kernel(const float* __restrict__ A,
                      const float* __restrict__ B,
                      const float* __restrict__ bias,
                      float* __restrict__ C,
                      int M, int N, int K) {
    extern __shared__ uint32_t sm[];
    uint32_t* AsBuf[2] = { sm, sm + AS_BUF };
    uint32_t* BsBuf[2] = { sm + 2 * AS_BUF, sm + 2 * AS_BUF + BS_BUF };

    const int tid = threadIdx.x;
    const int wid = tid >> 5;
    const int lane = tid & 31;
    const int r = lane >> 2;   // 0..7
    const int c = lane & 3;    // 0..3
    const int wm = (wid >> 2) * 64;   // 0 or 64
    const int wn = (wid & 3) * 32;    // 0..96
    const int row0 = blockIdx.y * 128;
    const int col0 = blockIdx.x * 128;

    // Global-load task decomposition (4 float4 each for A and B per thread)
    int am[4], ak[4], bk[4], bn[4];
#pragma unroll
    for (int i = 0; i < 4; i++) {
        int idx = tid + i * 256;
        am[i] = idx >> 3;            // 0..127
        ak[i] = (idx & 7) * 4;       // 0..28
        bk[i] = idx >> 5;            // 0..31
        bn[i] = (idx & 31) * 4;      // 0..124
    }

    float acc[4][4][4];
#pragma unroll
    for (int mt = 0; mt < 4; mt++)
#pragma unroll
        for (int nt = 0; nt < 4; nt++)
#pragma unroll
            for (int j = 0; j < 4; j++) acc[mt][nt][j] = 0.0f;

    float4 ra[4], rb[4];
    const int nch = K >> 5;  // K/32

    // Prologue: load chunk 0
    {
        const float* Ap = A + (size_t)row0 * K;
        const float* Bp = B + col0;
#pragma unroll
        for (int i = 0; i < 4; i++) {
            ra[i] = *(const float4*)(Ap + (size_t)am[i] * K + ak[i]);
            rb[i] = *(const float4*)(Bp + (size_t)bk[i] * N + bn[i]);
        }
#pragma unroll
        for (int i = 0; i < 4; i++) {
            uint4 va = make_uint4(f2tf32(ra[i].x), f2tf32(ra[i].y), f2tf32(ra[i].z), f2tf32(ra[i].w));
            *(uint4*)&AsBuf[0][am[i] * GA_PAD + ak[i]] = va;
            uint4 vb = make_uint4(f2tf32(rb[i].x), f2tf32(rb[i].y), f2tf32(rb[i].z), f2tf32(rb[i].w));
            *(uint4*)&BsBuf[0][bk[i] * GB_PAD + bn[i]] = vb;
        }
    }
    __syncthreads();

    for (int ch = 0; ch < nch; ch++) {
        const int buf = ch & 1;
        // Prefetch next chunk into registers (overlaps with compute below)
        if (ch + 1 < nch) {
            const float* Ap = A + (size_t)row0 * K + (ch + 1) * 32;
            const float* Bp = B + (size_t)((ch + 1) * 32) * N + col0;
#pragma unroll
            for (int i = 0; i < 4; i++) {
                ra[i] = *(const float4*)(Ap + (size_t)am[i] * K + ak[i]);
                rb[i] = *(const float4*)(Bp + (size_t)bk[i] * N + bn[i]);
            }
        }

        // Compute on current buffer
        const uint32_t* As = AsBuf[buf];
        const uint32_t* Bs = BsBuf[buf];
#pragma unroll
        for (int ks = 0; ks < 4; ks++) {
            const int kb = ks * 8;
            uint32_t af[4][4], bf[4][2];
#pragma unroll
            for (int mt = 0; mt < 4; mt++) {
                int row = wm + mt * 16 + r;
                af[mt][0] = As[row * GA_PAD + kb + c];
                af[mt][1] = As[(row + 8) * GA_PAD + kb + c];
                af[mt][2] = As[row * GA_PAD + kb + c + 4];
                af[mt][3] = As[(row + 8) * GA_PAD + kb + c + 4];
            }
#pragma unroll
            for (int nt = 0; nt < 4; nt++) {
                int col = wn + nt * 8 + r;
                bf[nt][0] = Bs[(kb + c) * GB_PAD + col];
                bf[nt][1] = Bs[(kb + c + 4) * GB_PAD + col];
            }
#pragma unroll
            for (int mt = 0; mt < 4; mt++)
#pragma unroll
                for (int nt = 0; nt < 4; nt++)
                    mma_tf32(acc[mt][nt], af[mt], bf[nt]);
        }

        // Stage next chunk into the other buffer
        if (ch + 1 < nch) {
            uint32_t* An = AsBuf[buf ^ 1];
            uint32_t* Bn = BsBuf[buf ^ 1];
#pragma unroll
            for (int i = 0; i < 4; i++) {
                uint4 va = make_uint4(f2tf32(ra[i].x), f2tf32(ra[i].y), f2tf32(ra[i].z), f2tf32(ra[i].w));
                *(uint4*)&An[am[i] * GA_PAD + ak[i]] = va;
                uint4 vb = make_uint4(f2tf32(rb[i].x), f2tf32(rb[i].y), f2tf32(rb[i].z), f2tf32(rb[i].w));
                *(uint4*)&Bn[bk[i] * GB_PAD + bn[i]] = vb;
            }
            __syncthreads();
        }
    }

    // Epilogue: bias + store
#pragma unroll
    for (int mt = 0; mt < 4; mt++) {
#pragma unroll
        for (int nt = 0; nt < 4; nt++) {
            int row = row0 + wm + mt * 16 + r;
            int col = col0 + wn + nt * 8 + c * 2;
            float2 bv = *(const float2*)(bias + col);
            float2 o0, o1;
            o0.x = acc[mt][nt][0] + bv.x;
            o0.y = acc[mt][nt][1] + bv.y;
            o1.x = acc[mt][nt][2] + bv.x;
            o1.y = acc[mt][nt][3] + bv.y;
            *(float2*)(C + (size_t)row * N + col) = o0;
            *(float2*)(C + (size_t)(row + 8) * N + col) = o1;
        }
    }
}

// ---------------------------------------------------------------------------
// Attention (fp32 SIMT flash-style; R4 optimization target)
// ---------------------------------------------------------------------------
__global__ __launch_bounds__(256, 2)
void attn_kernel(const float* __restrict__ qkv,
                 const float* __restrict__ pqkv,
                 float* __restrict__ y) {
    extern __shared__ float smf[];
    float (*Qs)[65]  = (float(*)[65])smf;
    float (*KVs)[65] = (float(*)[65])(smf + 64 * 65);
    float (*Ps)[65]  = (float(*)[65])(smf + 2 * 64 * 65);

    const int bh = blockIdx.x;
    const int b = bh / NHEAD;
    const int h = bh % NHEAD;
    const int qt = blockIdx.y;
    const int tid = threadIdx.x;
    const int tx = tid & 15;
    const int ty = tid >> 4;
    const float scale = 0.125f;

    const float* qbase = qkv + (size_t)(b * SEQ_T + qt * 64) * C3 + h * HDIM;
#pragma unroll
    for (int i = 0; i < 4; i++) {
        int lin = tid + i * 256;
        int r = lin >> 4;
        int c4 = (lin & 15) * 4;
        float4 v = *(const float4*)(qbase + (size_t)r * C3 + c4);
        Qs[r][c4] = v.x; Qs[r][c4 + 1] = v.y; Qs[r][c4 + 2] = v.z; Qs[r][c4 + 3] = v.w;
    }

    float out[4][4];
#pragma unroll
    for (int r = 0; r < 4; r++)
#pragma unroll
        for (int c = 0; c < 4; c++) out[r][c] = 0.0f;

    for (int pass = 0; pass < 2; pass++) {
        float m[4], l[4], o[4][4];
#pragma unroll
        for (int r = 0; r < 4; r++) {
            m[r] = -1e30f; l[r] = 0.0f;
#pragma unroll
            for (int c = 0; c < 4; c++) o[r][c] = 0.0f;
        }
        const int ntiles = (pass == 0) ? (qt + 1) : 1;
        const float* src = (pass == 0) ? qkv : pqkv;
        const int rowbase = (pass == 0) ? (b * SEQ_T) : (b * SEQ_TP);

        for (int kt = 0; kt < ntiles; kt++) {
            __syncthreads();
            const float* kbase = src + (size_t)(rowbase + kt * 64) * C3 + CH + h * HDIM;
#pragma unroll
            for (int i = 0; i < 4; i++) {
                int lin = tid + i * 256;
                int r = lin >> 4;
                int c4 = (lin & 15) * 4;
                float4 v = *(const float4*)(kbase + (size_t)r * C3 + c4);
                KVs[r][c4] = v.x; KVs[r][c4 + 1] = v.y; KVs[r][c4 + 2] = v.z; KVs[r][c4 + 3] = v.w;
            }
            __syncthreads();

            float S[4][4];
#pragma unroll
            for (int r = 0; r < 4; r++)
#pragma unroll
                for (int c = 0; c < 4; c++) S[r][c] = 0.0f;
#pragma unroll 8
            for (int k = 0; k < 64; k++) {
                float a[4], bb[4];
#pragma unroll
                for (int r = 0; r < 4; r++) a[r] = Qs[ty * 4 + r][k];
#pragma unroll
                for (int c = 0; c < 4; c++) bb[c] = KVs[tx * 4 + c][k];
#pragma unroll
                for (int r = 0; r < 4; r++)
#pragma unroll
                    for (int c = 0; c < 4; c++) S[r][c] += a[r] * bb[c];
            }

            const bool need_mask = (pass == 0) ? (kt == qt) : (qt == 0);
            const int qg0 = qt * 64 + ty * 4;
            const int kg0 = kt * 64 + tx * 4;
#pragma unroll
            for (int r = 0; r < 4; r++)
#pragma unroll
                for (int c = 0; c < 4; c++) {
                    float s = S[r][c] * scale;
                    if (need_mask && (kg0 + c > qg0 + r)) s = -1e30f;
                    S[r][c] = s;
                }

#pragma unroll
            for (int r = 0; r < 4; r++) {
                float mx = fmaxf(fmaxf(S[r][0], S[r][1]), fmaxf(S[r][2], S[r][3]));
#pragma unroll
                for (int off = 8; off >= 1; off >>= 1)
                    mx = fmaxf(mx, __shfl_xor_sync(0xffffffffu, mx, off));
                float mnew = fmaxf(m[r], mx);
                float alpha = __expf(m[r] - mnew);
                m[r] = mnew;
                float rs = 0.0f;
#pragma unroll
                for (int c = 0; c < 4; c++) {
                    float p = __expf(S[r][c] - mnew);
                    S[r][c] = p;
                    rs += p;
                }
#pragma unroll
                for (int off = 8; off >= 1; off >>= 1)
                    rs += __shfl_xor_sync(0xffffffffu, rs, off);
                l[r] = l[r] * alpha + rs;
#pragma unroll
                for (int c = 0; c < 4; c++) o[r][c] *= alpha;
            }

#pragma unroll
            for (int r = 0; r < 4; r++)
#pragma unroll
                for (int c = 0; c < 4; c++) Ps[ty * 4 + r][tx * 4 + c] = S[r][c];
            __syncthreads();

            const float* vbase = kbase + CH;
#pragma unroll
            for (int i = 0; i < 4; i++) {
                int lin = tid + i * 256;
                int r = lin >> 4;
                int c4 = (lin & 15) * 4;
                float4 v = *(const float4*)(vbase + (size_t)r * C3 + c4);
                KVs[r][c4] = v.x; KVs[r][c4 + 1] = v.y; KVs[r][c4 + 2] = v.z; KVs[r][c4 + 3] = v.w;
            }
            __syncthreads();

#pragma unroll 8
            for (int k = 0; k < 64; k++) {
                float p[4], vv[4];
#pragma unroll
                for (int r = 0; r < 4; r++) p[r] = Ps[ty * 4 + r][k];
#pragma unroll
                for (int c = 0; c < 4; c++) vv[c] = KVs[k][tx * 4 + c];
#pragma unroll
                for (int r = 0; r < 4; r++)
#pragma unroll
                    for (int c = 0; c < 4; c++) o[r][c] += p[r] * vv[c];
            }
        }

#pragma unroll
        for (int r = 0; r < 4; r++) {
            float inv = 1.0f / l[r];
#pragma unroll
            for (int c = 0; c < 4; c++) out[r][c] += o[r][c] * inv;
        }
    }

#pragma unroll
    for (int r = 0; r < 4; r++) {
        int qg = qt * 64 + ty * 4 + r;
        float* yp = y + (size_t)(b * SEQ_T + qg) * CH + h * HDIM + tx * 4;
        float4 o4;
        o4.x = out[r][0]; o4.y = out[r][1]; o4.z = out[r][2]; o4.w = out[r][3];
        *(float4*)yp = o4;
    }
}

// ---------------------------------------------------------------------------
// Launch
// ---------------------------------------------------------------------------
extern "C" void kernel_launch(void* const* d_in, const int* in_sizes, int n_in,
                              void* d_out, int out_size) {
    const float* x        = (const float*)d_in[0];
    const float* prefix   = (const float*)d_in[1];
    const float* w_attn   = (const float*)d_in[2];
    const float* b_attn   = (const float*)d_in[3];
    const float* w_prefix = (const float*)d_in[4];
    const float* b_prefix = (const float*)d_in[5];
    const float* w_proj   = (const float*)d_in[6];
    const float* b_proj   = (const float*)d_in[7];
    float* out = (float*)d_out;

    float *qkv_ptr, *pqkv_ptr, *y_ptr;
    cudaGetSymbolAddress((void**)&qkv_ptr, g_qkv);
    cudaGetSymbolAddress((void**)&pqkv_ptr, g_pqkv);
    cudaGetSymbolAddress((void**)&y_ptr, g_y);

    cudaFuncSetAttribute(gemm_tf32_kernel, cudaFuncAttributeMaxDynamicSharedMemorySize, GEMM_SMEM);
    const int smem_attn = 3 * 64 * 65 * sizeof(float);
    cudaFuncSetAttribute(attn_kernel, cudaFuncAttributeMaxDynamicSharedMemorySize, smem_attn);

    // 1) qkv = x @ w_attn + b_attn : (8192,1024)x(1024,3072)
    {
        dim3 grid(C3 / 128, (BATCH * SEQ_T) / 128);
        gemm_tf32_kernel<<<grid, 256, GEMM_SMEM>>>(x, w_attn, b_attn, qkv_ptr,
                                                   BATCH * SEQ_T, C3, CH);
    }
    // 2) pqkv = prefix @ w_prefix + b_prefix : (512,1024)x(1024,3072)
    {
        dim3 grid(C3 / 128, (BATCH * SEQ_TP) / 128);
        gemm_tf32_kernel<<<grid, 256, GEMM_SMEM>>>(prefix, w_prefix, b_prefix, pqkv_ptr,
                                                   BATCH * SEQ_TP, C3, CH);
    }
    // 3) attention -> y
    {
        dim3 grid(BATCH * NHEAD, SEQ_T / 64);
        attn_kernel<<<grid, 256, smem_attn>>>(qkv_ptr, pqkv_ptr, y_ptr);
    }
    // 4) out = y @ w_proj + b_proj : (8192,1024)x(1024,1024)
    {
        dim3 grid(CH / 128, (BATCH * SEQ_T) / 128);
        gemm_tf32_kernel<<<grid, 256, GEMM_SMEM>>>(y_ptr, w_proj, b_proj, out,
                                                   BATCH * SEQ_T, CH, CH);
    }
}

// round 5
// speedup vs baseline: 3.2223x; 2.1517x over previous
#include <cuda_runtime.h>
#include <math.h>
#include <stdint.h>

// Problem constants
#define BATCH 8
#define SEQ_T 1024
#define SEQ_TP 64
#define CH 1024
#define NHEAD 16
#define HDIM 64
#define C3 (3 * CH)

// Scratch (device globals: allocation-free rule)
__device__ float g_qkv[BATCH * SEQ_T * C3];    // (8192, 3072)
__device__ float g_pqkv[BATCH * SEQ_TP * C3];  // (512, 3072)
__device__ float g_y[BATCH * SEQ_T * CH];      // (8192, 1024)

// ===========================================================================
// helpers (compute_80+ features only)
// ===========================================================================
__device__ __forceinline__ uint32_t f2tf32(float f) {
    uint32_t r;
    asm("cvt.rna.tf32.f32 %0, %1;" : "=r"(r) : "f"(f));
    return r;
}

__device__ __forceinline__ void mma_tf32(float* d, const uint32_t* a, const uint32_t* b) {
    asm volatile(
        "mma.sync.aligned.m16n8k8.row.col.f32.tf32.tf32.f32 "
        "{%0,%1,%2,%3}, {%4,%5,%6,%7}, {%8,%9}, {%0,%1,%2,%3};"
        : "+f"(d[0]), "+f"(d[1]), "+f"(d[2]), "+f"(d[3])
        : "r"(a[0]), "r"(a[1]), "r"(a[2]), "r"(a[3]), "r"(b[0]), "r"(b[1]));
}

__device__ __forceinline__ uint32_t smem_u32(const void* p) {
    uint32_t a;
    asm("{ .reg .u64 t; cvta.to.shared.u64 t, %1; cvt.u32.u64 %0, t; }"
        : "=r"(a) : "l"(p));
    return a;
}

__device__ __forceinline__ void cp16(uint32_t dst, const void* src) {
    asm volatile("cp.async.cg.shared.global [%0], [%1], 16;" :: "r"(dst), "l"(src));
}
#define CP_COMMIT() asm volatile("cp.async.commit_group;" ::: "memory")
#define CP_WAIT(n)  asm volatile("cp.async.wait_group %0;" :: "n"(n) : "memory")

// ===========================================================================
// tf32 tensor-core GEMM: C[M,N] = A[M,K] @ B[K,N] + bias[N], fp32 in/out.
// Block 128x128, BK=32, 256 thr (8 warps 2x4, warp tile 64x32).
// 2-stage cp.async ring; raw fp32 in smem; cvt->tf32 at fragment load.
// ===========================================================================
#define GA_PAD 36
#define GB_PAD 136
#define ASZ (128 * GA_PAD)   // floats per A stage
#define BSZ (32 * GB_PAD)    // floats per B stage
#define GEMM_SMEM ((2 * ASZ + 2 * BSZ) * 4)  // 71680 bytes

__global__ __launch_bounds__(256)
void gemm_tf32_kernel(const float* __restrict__ A,
                      const float* __restrict__ B,
                      const float* __restrict__ bias,
                      float* __restrict__ C,
                      int M, int N, int K) {
    extern __shared__ float smf[];
    const uint32_t sm_b = smem_u32(smf);

    const int tid = threadIdx.x;
    const int wid = tid >> 5;
    const int lane = tid & 31;
    const int r = lane >> 2;
    const int c = lane & 3;
    const int wm = (wid >> 2) * 64;
    const int wn = (wid & 3) * 32;
    const int row0 = blockIdx.y * 128;
    const int col0 = blockIdx.x * 128;

    float acc[4][4][4];
#pragma unroll
    for (int mt = 0; mt < 4; mt++)
#pragma unroll
        for (int nt = 0; nt < 4; nt++)
#pragma unroll
            for (int j = 0; j < 4; j++) acc[mt][nt][j] = 0.0f;

    const int nch = K >> 5;

    auto load_stage = [&](int ch, int st) {
#pragma unroll
        for (int i = 0; i < 4; i++) {
            int idx = tid + i * 256;
            int rw = idx >> 3;
            int k4 = (idx & 7) * 4;
            uint32_t dst = sm_b + (uint32_t)((st * ASZ + rw * GA_PAD + k4) * 4);
            cp16(dst, A + (size_t)(row0 + rw) * K + ch * 32 + k4);
        }
#pragma unroll
        for (int i = 0; i < 4; i++) {
            int idx = tid + i * 256;
            int kk = idx >> 5;
            int n4 = (idx & 31) * 4;
            uint32_t dst = sm_b + (uint32_t)((2 * ASZ + st * BSZ + kk * GB_PAD + n4) * 4);
            cp16(dst, B + (size_t)(ch * 32 + kk) * N + col0 + n4);
        }
        CP_COMMIT();
    };

    load_stage(0, 0);
    if (nch > 1) load_stage(1, 1);

    for (int ch = 0; ch < nch; ch++) {
        if (ch + 1 < nch) { CP_WAIT(1); } else { CP_WAIT(0); }
        __syncthreads();

        const int buf = ch & 1;
        const float* Asf = smf + buf * ASZ;
        const float* Bsf = smf + 2 * ASZ + buf * BSZ;
#pragma unroll
        for (int ks = 0; ks < 4; ks++) {
            const int kb = ks * 8;
            uint32_t af[4][4], bf[4][2];
#pragma unroll
            for (int mt = 0; mt < 4; mt++) {
                int row = wm + mt * 16 + r;
                af[mt][0] = f2tf32(Asf[row * GA_PAD + kb + c]);
                af[mt][1] = f2tf32(Asf[(row + 8) * GA_PAD + kb + c]);
                af[mt][2] = f2tf32(Asf[row * GA_PAD + kb + c + 4]);
                af[mt][3] = f2tf32(Asf[(row + 8) * GA_PAD + kb + c + 4]);
            }
#pragma unroll
            for (int nt = 0; nt < 4; nt++) {
                int col = wn + nt * 8 + r;
                bf[nt][0] = f2tf32(Bsf[(kb + c) * GB_PAD + col]);
                bf[nt][1] = f2tf32(Bsf[(kb + c + 4) * GB_PAD + col]);
            }
#pragma unroll
            for (int mt = 0; mt < 4; mt++)
#pragma unroll
                for (int nt = 0; nt < 4; nt++)
                    mma_tf32(acc[mt][nt], af[mt], bf[nt]);
        }
        __syncthreads();
        if (ch + 2 < nch) load_stage(ch + 2, buf);
    }

    // Epilogue: bias + store
#pragma unroll
    for (int mt = 0; mt < 4; mt++) {
#pragma unroll
        for (int nt = 0; nt < 4; nt++) {
            int row = row0 + wm + mt * 16 + r;
            int col = col0 + wn + nt * 8 + c * 2;
            float2 bv = *(const float2*)(bias + col);
            float2 o0, o1;
            o0.x = acc[mt][nt][0] + bv.x;
            o0.y = acc[mt][nt][1] + bv.y;
            o1.x = acc[mt][nt][2] + bv.x;
            o1.y = acc[mt][nt][3] + bv.y;
            *(float2*)(C + (size_t)row * N + col) = o0;
            *(float2*)(C + (size_t)(row + 8) * N + col) = o1;
        }
    }
}

// ===========================================================================
// Attention with tf32 mma (FA2-style fragment softmax).
// Grid (B*H, T/64), 128 threads (4 warps); warp w owns rows w*16..w*16+15.
// Tiles are 64 cols wide -> pads 68/72 (>=64, same residues mod 32 as GEMM
// pads so all fragment access patterns stay conflict-free).
// Dynamic smem: (2*64*68 + 64*72 + 64*68) * 4 = 70656 bytes.
// ===========================================================================
#define QS_PAD 68
#define VS_PAD 72
#define ATT_QS  (64 * QS_PAD)
#define ATT_KS  (64 * QS_PAD)
#define ATT_VS  (64 * VS_PAD)
#define ATT_PS  (64 * QS_PAD)
#define ATT_SMEM ((ATT_QS + ATT_KS + ATT_VS + ATT_PS) * 4)

__global__ __launch_bounds__(128)
void attn_mma_kernel(const float* __restrict__ qkv,
                     const float* __restrict__ pqkv,
                     float* __restrict__ y) {
    extern __shared__ uint32_t smu[];
    uint32_t* Qs = smu;
    uint32_t* Ks = smu + ATT_QS;
    uint32_t* Vs = smu + ATT_QS + ATT_KS;
    uint32_t* Ps = smu + ATT_QS + ATT_KS + ATT_VS;

    const int bh = blockIdx.x;
    const int b = bh / NHEAD;
    const int h = bh % NHEAD;
    const int qt = blockIdx.y;
    const int tid = threadIdx.x;
    const int w = tid >> 5;
    const int lane = tid & 31;
    const int r = lane >> 2;
    const int c = lane & 3;
    const float scale = 0.125f;

    // Load Q tile (64x64) -> tf32 smem
    const float* qbase = qkv + (size_t)(b * SEQ_T + qt * 64) * C3 + h * HDIM;
#pragma unroll
    for (int i = 0; i < 8; i++) {
        int idx = tid + i * 128;
        int row = idx >> 4;
        int c4 = (idx & 15) * 4;
        float4 v = *(const float4*)(qbase + (size_t)row * C3 + c4);
        uint4 t = make_uint4(f2tf32(v.x), f2tf32(v.y), f2tf32(v.z), f2tf32(v.w));
        *(uint4*)&Qs[row * QS_PAD + c4] = t;
    }

    float out[8][4];
#pragma unroll
    for (int nt = 0; nt < 8; nt++)
#pragma unroll
        for (int j = 0; j < 4; j++) out[nt][j] = 0.0f;

    const int gr0 = qt * 64 + w * 16 + r;
    const int gr1 = gr0 + 8;

    for (int pass = 0; pass < 2; pass++) {
        const int ntiles = (pass == 0) ? (qt + 1) : 1;
        const float* src = (pass == 0) ? qkv : pqkv;
        const int rowbase = (pass == 0) ? (b * SEQ_T) : (b * SEQ_TP);

        float m0 = -1e30f, m1 = -1e30f, l0 = 0.0f, l1 = 0.0f;
        float o[8][4];
#pragma unroll
        for (int nt = 0; nt < 8; nt++)
#pragma unroll
            for (int j = 0; j < 4; j++) o[nt][j] = 0.0f;

        for (int kt = 0; kt < ntiles; kt++) {
            __syncthreads();
            // Load K, V tiles -> tf32 smem
            const float* kb = src + (size_t)(rowbase + kt * 64) * C3 + CH + h * HDIM;
            const float* vb = kb + CH;
#pragma unroll
            for (int i = 0; i < 8; i++) {
                int idx = tid + i * 128;
                int row = idx >> 4;
                int c4 = (idx & 15) * 4;
                float4 v = *(const float4*)(kb + (size_t)row * C3 + c4);
                uint4 t = make_uint4(f2tf32(v.x), f2tf32(v.y), f2tf32(v.z), f2tf32(v.w));
                *(uint4*)&Ks[row * QS_PAD + c4] = t;
                float4 u = *(const float4*)(vb + (size_t)row * C3 + c4);
                uint4 s = make_uint4(f2tf32(u.x), f2tf32(u.y), f2tf32(u.z), f2tf32(u.w));
                *(uint4*)&Vs[row * VS_PAD + c4] = s;
            }
            __syncthreads();

            // S = Q K^T
            float s[8][4];
#pragma unroll
            for (int nt = 0; nt < 8; nt++)
#pragma unroll
                for (int j = 0; j < 4; j++) s[nt][j] = 0.0f;
#pragma unroll
            for (int ks = 0; ks < 8; ks++) {
                const int kbb = ks * 8;
                uint32_t aq[4];
                int rowA = w * 16 + r;
                aq[0] = Qs[rowA * QS_PAD + kbb + c];
                aq[1] = Qs[(rowA + 8) * QS_PAD + kbb + c];
                aq[2] = Qs[rowA * QS_PAD + kbb + c + 4];
                aq[3] = Qs[(rowA + 8) * QS_PAD + kbb + c + 4];
#pragma unroll
                for (int nt = 0; nt < 8; nt++) {
                    uint32_t bk[2];
                    bk[0] = Ks[(nt * 8 + r) * QS_PAD + kbb + c];
                    bk[1] = Ks[(nt * 8 + r) * QS_PAD + kbb + c + 4];
                    mma_tf32(s[nt], aq, bk);
                }
            }

            // scale + causal mask
            const int cbase = (pass == 0) ? kt * 64 : 0;
#pragma unroll
            for (int nt = 0; nt < 8; nt++) {
                int gc = cbase + nt * 8 + 2 * c;
                s[nt][0] = (gc     > gr0) ? -1e30f : s[nt][0] * scale;
                s[nt][1] = (gc + 1 > gr0) ? -1e30f : s[nt][1] * scale;
                s[nt][2] = (gc     > gr1) ? -1e30f : s[nt][2] * scale;
                s[nt][3] = (gc + 1 > gr1) ? -1e30f : s[nt][3] * scale;
            }

            // online softmax (rows gr0, gr1; 4 lanes per row share via quad shfl)
            float mx0 = -1e30f, mx1 = -1e30f;
#pragma unroll
            for (int nt = 0; nt < 8; nt++) {
                mx0 = fmaxf(mx0, fmaxf(s[nt][0], s[nt][1]));
                mx1 = fmaxf(mx1, fmaxf(s[nt][2], s[nt][3]));
            }
            mx0 = fmaxf(mx0, __shfl_xor_sync(0xffffffffu, mx0, 1));
            mx0 = fmaxf(mx0, __shfl_xor_sync(0xffffffffu, mx0, 2));
            mx1 = fmaxf(mx1, __shfl_xor_sync(0xffffffffu, mx1, 1));
            mx1 = fmaxf(mx1, __shfl_xor_sync(0xffffffffu, mx1, 2));

            float mn0 = fmaxf(m0, mx0);
            float mn1 = fmaxf(m1, mx1);
            float a0 = __expf(m0 - mn0);
            float a1 = __expf(m1 - mn1);
            m0 = mn0; m1 = mn1;

            float rs0 = 0.0f, rs1 = 0.0f;
#pragma unroll
            for (int nt = 0; nt < 8; nt++) {
                s[nt][0] = __expf(s[nt][0] - mn0);
                s[nt][1] = __expf(s[nt][1] - mn0);
                s[nt][2] = __expf(s[nt][2] - mn1);
                s[nt][3] = __expf(s[nt][3] - mn1);
                rs0 += s[nt][0] + s[nt][1];
                rs1 += s[nt][2] + s[nt][3];
            }
            rs0 += __shfl_xor_sync(0xffffffffu, rs0, 1);
            rs0 += __shfl_xor_sync(0xffffffffu, rs0, 2);
            rs1 += __shfl_xor_sync(0xffffffffu, rs1, 1);
            rs1 += __shfl_xor_sync(0xffffffffu, rs1, 2);
            l0 = l0 * a0 + rs0;
            l1 = l1 * a1 + rs1;
#pragma unroll
            for (int nt = 0; nt < 8; nt++) {
                o[nt][0] *= a0; o[nt][1] *= a0;
                o[nt][2] *= a1; o[nt][3] *= a1;
            }

            // stage P (tf32) into per-warp smem slice
            {
                int rowA = w * 16 + r;
#pragma unroll
                for (int nt = 0; nt < 8; nt++) {
                    uint2 p0 = make_uint2(f2tf32(s[nt][0]), f2tf32(s[nt][1]));
                    uint2 p1 = make_uint2(f2tf32(s[nt][2]), f2tf32(s[nt][3]));
                    *(uint2*)&Ps[rowA * QS_PAD + nt * 8 + 2 * c] = p0;
                    *(uint2*)&Ps[(rowA + 8) * QS_PAD + nt * 8 + 2 * c] = p1;
                }
            }
            __syncwarp();

            // O += P V
#pragma unroll
            for (int ks = 0; ks < 8; ks++) {
                const int kbb = ks * 8;
                uint32_t ap[4];
                int rowA = w * 16 + r;
                ap[0] = Ps[rowA * QS_PAD + kbb + c];
                ap[1] = Ps[(rowA + 8) * QS_PAD + kbb + c];
                ap[2] = Ps[rowA * QS_PAD + kbb + c + 4];
                ap[3] = Ps[(rowA + 8) * QS_PAD + kbb + c + 4];
#pragma unroll
                for (int nt = 0; nt < 8; nt++) {
                    uint32_t bv[2];
                    bv[0] = Vs[(kbb + c) * VS_PAD + nt * 8 + r];
                    bv[1] = Vs[(kbb + c + 4) * VS_PAD + nt * 8 + r];
                    mma_tf32(o[nt], ap, bv);
                }
            }
        }

        // normalize & accumulate
        float inv0 = 1.0f / l0;
        float inv1 = 1.0f / l1;
#pragma unroll
        for (int nt = 0; nt < 8; nt++) {
            out[nt][0] += o[nt][0] * inv0;
            out[nt][1] += o[nt][1] * inv0;
            out[nt][2] += o[nt][2] * inv1;
            out[nt][3] += o[nt][3] * inv1;
        }
    }

    // Write y
    {
        float* y0 = y + (size_t)(b * SEQ_T + gr0) * CH + h * HDIM;
        float* y1 = y + (size_t)(b * SEQ_T + gr1) * CH + h * HDIM;
#pragma unroll
        for (int nt = 0; nt < 8; nt++) {
            int col = nt * 8 + 2 * c;
            *(float2*)(y0 + col) = make_float2(out[nt][0], out[nt][1]);
            *(float2*)(y1 + col) = make_float2(out[nt][2], out[nt][3]);
        }
    }
}

// ---------------------------------------------------------------------------
// Launch
// ---------------------------------------------------------------------------
extern "C" void kernel_launch(void* const* d_in, const int* in_sizes, int n_in,
                              void* d_out, int out_size) {
    const float* x        = (const float*)d_in[0];
    const float* prefix   = (const float*)d_in[1];
    const float* w_attn   = (const float*)d_in[2];
    const float* b_attn   = (const float*)d_in[3];
    const float* w_prefix = (const float*)d_in[4];
    const float* b_prefix = (const float*)d_in[5];
    const float* w_proj   = (const float*)d_in[6];
    const float* b_proj   = (const float*)d_in[7];
    float* out = (float*)d_out;

    float *qkv_ptr, *pqkv_ptr, *y_ptr;
    cudaGetSymbolAddress((void**)&qkv_ptr, g_qkv);
    cudaGetSymbolAddress((void**)&pqkv_ptr, g_pqkv);
    cudaGetSymbolAddress((void**)&y_ptr, g_y);

    cudaFuncSetAttribute(gemm_tf32_kernel, cudaFuncAttributeMaxDynamicSharedMemorySize, GEMM_SMEM);
    cudaFuncSetAttribute(attn_mma_kernel, cudaFuncAttributeMaxDynamicSharedMemorySize, ATT_SMEM);

    // 1) qkv = x @ w_attn + b_attn
    {
        dim3 grid(C3 / 128, (BATCH * SEQ_T) / 128);
        gemm_tf32_kernel<<<grid, 256, GEMM_SMEM>>>(x, w_attn, b_attn, qkv_ptr,
                                                   BATCH * SEQ_T, C3, CH);
    }
    // 2) pqkv = prefix @ w_prefix + b_prefix
    {
        dim3 grid(C3 / 128, (BATCH * SEQ_TP) / 128);
        gemm_tf32_kernel<<<grid, 256, GEMM_SMEM>>>(prefix, w_prefix, b_prefix, pqkv_ptr,
                                                   BATCH * SEQ_TP, C3, CH);
    }
    // 3) attention -> y
    {
        dim3 grid(BATCH * NHEAD, SEQ_T / 64);
        attn_mma_kernel<<<grid, 128, ATT_SMEM>>>(qkv_ptr, pqkv_ptr, y_ptr);
    }
    // 4) out = y @ w_proj + b_proj
    {
        dim3 grid(CH / 128, (BATCH * SEQ_T) / 128);
        gemm_tf32_kernel<<<grid, 256, GEMM_SMEM>>>(y_ptr, w_proj, b_proj, out,
                                                   BATCH * SEQ_T, CH, CH);
    }
}

// round 6
// speedup vs baseline: 3.6905x; 1.1453x over previous
#include <cuda_runtime.h>
#include <math.h>
#include <stdint.h>

// Problem constants
#define BATCH 8
#define SEQ_T 1024
#define SEQ_TP 64
#define CH 1024
#define NHEAD 16
#define HDIM 64
#define C3 (3 * CH)

// Scratch (device globals: allocation-free rule)
__device__ float g_qkv[BATCH * SEQ_T * C3];    // (8192, 3072)
__device__ float g_pqkv[BATCH * SEQ_TP * C3];  // (512, 3072)
__device__ float g_y[BATCH * SEQ_T * CH];      // (8192, 1024)

// ===========================================================================
// helpers (compute_80+ features only)
// ===========================================================================
__device__ __forceinline__ uint32_t f2tf32(float f) {
    uint32_t r;
    asm("cvt.rna.tf32.f32 %0, %1;" : "=r"(r) : "f"(f));
    return r;
}

__device__ __forceinline__ void mma_tf32(float* d, const uint32_t* a, const uint32_t* b) {
    asm volatile(
        "mma.sync.aligned.m16n8k8.row.col.f32.tf32.tf32.f32 "
        "{%0,%1,%2,%3}, {%4,%5,%6,%7}, {%8,%9}, {%0,%1,%2,%3};"
        : "+f"(d[0]), "+f"(d[1]), "+f"(d[2]), "+f"(d[3])
        : "r"(a[0]), "r"(a[1]), "r"(a[2]), "r"(a[3]), "r"(b[0]), "r"(b[1]));
}

__device__ __forceinline__ void mma_f16(float* d, const uint32_t* a, const uint32_t* b) {
    asm volatile(
        "mma.sync.aligned.m16n8k16.row.col.f32.f16.f16.f32 "
        "{%0,%1,%2,%3}, {%4,%5,%6,%7}, {%8,%9}, {%0,%1,%2,%3};"
        : "+f"(d[0]), "+f"(d[1]), "+f"(d[2]), "+f"(d[3])
        : "r"(a[0]), "r"(a[1]), "r"(a[2]), "r"(a[3]), "r"(b[0]), "r"(b[1]));
}

__device__ __forceinline__ void ldsm_x4(uint32_t* r, uint32_t addr) {
    asm volatile(
        "ldmatrix.sync.aligned.m8n8.x4.shared.b16 {%0,%1,%2,%3}, [%4];"
        : "=r"(r[0]), "=r"(r[1]), "=r"(r[2]), "=r"(r[3]) : "r"(addr));
}

__device__ __forceinline__ void ldsm_x4_t(uint32_t* r, uint32_t addr) {
    asm volatile(
        "ldmatrix.sync.aligned.m8n8.x4.trans.shared.b16 {%0,%1,%2,%3}, [%4];"
        : "=r"(r[0]), "=r"(r[1]), "=r"(r[2]), "=r"(r[3]) : "r"(addr));
}

// pack {hi, lo} -> f16x2 (lo in lower half)
__device__ __forceinline__ uint32_t pack_f16(float hi, float lo) {
    uint32_t h;
    asm("cvt.rn.f16x2.f32 %0, %1, %2;" : "=r"(h) : "f"(hi), "f"(lo));
    return h;
}

__device__ __forceinline__ uint32_t smem_u32(const void* p) {
    uint32_t a;
    asm("{ .reg .u64 t; cvta.to.shared.u64 t, %1; cvt.u32.u64 %0, t; }"
        : "=r"(a) : "l"(p));
    return a;
}

__device__ __forceinline__ void cp16(uint32_t dst, const void* src) {
    asm volatile("cp.async.cg.shared.global [%0], [%1], 16;" :: "r"(dst), "l"(src));
}
#define CP_COMMIT() asm volatile("cp.async.commit_group;" ::: "memory")
#define CP_WAIT(n)  asm volatile("cp.async.wait_group %0;" :: "n"(n) : "memory")

// ===========================================================================
// fp16 tensor-core GEMM: C[M,N] = A[M,K] @ B[K,N] + bias[N], fp32 in/out.
// Block 128x128, BK=32, 256 thr (8 warps 2x4, warp tile 64x32).
// cp.async fp32 stages (2) -> convert pass to packed fp16 stages (2)
// -> ldmatrix + mma.m16n8k16.
// fp16 A layout: [128 rows][32 k] pad 40 halfs (80B row; LDSM conflict-free).
// fp16 B layout: [32 k][128 n] pad 136 halfs (272B row; LDSM conflict-free).
// ===========================================================================
#define AF32P 36
#define BF32P 136
#define ASZ32 (128 * AF32P)          // 4608 u32 per fp32 A stage
#define BSZ32 (32 * BF32P)           // 4352 u32 per fp32 B stage
#define A16RP 20                     // u32 per A16 row (40 halfs)
#define B16RP 68                     // u32 per B16 row (136 halfs)
#define A16SZ (128 * A16RP)          // 2560 u32
#define B16SZ (32 * B16RP)           // 2176 u32
#define AF32_OFF 0
#define BF32_OFF (2 * ASZ32)                     // 9216
#define A16_OFF  (BF32_OFF + 2 * BSZ32)          // 17920
#define B16_OFF  (A16_OFF + 2 * A16SZ)           // 23040
#define GEMM_SMEM ((B16_OFF + 2 * B16SZ) * 4)    // 109568 bytes

__global__ __launch_bounds__(256)
void gemm_f16_kernel(const float* __restrict__ A,
                     const float* __restrict__ B,
                     const float* __restrict__ bias,
                     float* __restrict__ C,
                     int M, int N, int K) {
    extern __shared__ float smf[];
    uint32_t* smu = (uint32_t*)smf;
    const uint32_t sm_b = smem_u32(smf);

    const int tid = threadIdx.x;
    const int wid = tid >> 5;
    const int lane = tid & 31;
    const int r = lane >> 2;
    const int c = lane & 3;
    const int wm = (wid >> 2) * 64;
    const int wn = (wid & 3) * 32;
    const int row0 = blockIdx.y * 128;
    const int col0 = blockIdx.x * 128;

    // LDSM lane-address components
    const int mat = lane >> 3;       // 0..3
    const int m8r = lane & 7;        // row within 8x8 matrix
    // A: matrix order [m0-7,k0-7],[m8-15,k0-7],[m0-7,k8-15],[m8-15,k8-15]
    const int a_mloc = (mat & 1) * 8 + m8r;        // + mt*16 + wm
    const int a_koffB = (mat >> 1) * 16;           // bytes (+ kk*32)
    // B: matrix order [k0-7,n0-7],[k8-15,n0-7],[k0-7,n8-15],[k8-15,n8-15]
    const int b_kloc = (mat & 1) * 8 + m8r;        // + kk*16
    const int b_nloc = (mat >> 1) * 8;             // + wn + nt16*16

    float acc[4][4][4];
#pragma unroll
    for (int mt = 0; mt < 4; mt++)
#pragma unroll
        for (int nt = 0; nt < 4; nt++)
#pragma unroll
            for (int j = 0; j < 4; j++) acc[mt][nt][j] = 0.0f;

    const int nch = K >> 5;

    auto load_stage = [&](int ch, int st) {
#pragma unroll
        for (int i = 0; i < 4; i++) {
            int idx = tid + i * 256;
            int rw = idx >> 3;
            int k4 = (idx & 7) * 4;
            uint32_t dst = sm_b + (uint32_t)((AF32_OFF + st * ASZ32 + rw * AF32P + k4) * 4);
            cp16(dst, A + (size_t)(row0 + rw) * K + ch * 32 + k4);
        }
#pragma unroll
        for (int i = 0; i < 4; i++) {
            int idx = tid + i * 256;
            int kk = idx >> 5;
            int n4 = (idx & 31) * 4;
            uint32_t dst = sm_b + (uint32_t)((BF32_OFF + st * BSZ32 + kk * BF32P + n4) * 4);
            cp16(dst, B + (size_t)(ch * 32 + kk) * N + col0 + n4);
        }
        CP_COMMIT();
    };

    load_stage(0, 0);
    if (nch > 1) load_stage(1, 1);

    for (int ch = 0; ch < nch; ch++) {
        const int buf = ch & 1;
        if (ch + 1 < nch) { CP_WAIT(1); } else { CP_WAIT(0); }
        __syncthreads();

        // ---- convert pass: fp32 stage -> packed fp16 stage ----
        {
            const float* Af = smf + AF32_OFF + buf * ASZ32;
            uint32_t* A16 = smu + A16_OFF + buf * A16SZ;
#pragma unroll
            for (int i = 0; i < 4; i++) {
                int g = tid + i * 256;
                int row = g & 127;
                int k4 = (g >> 7) * 4;
                float4 v = *(const float4*)(Af + row * AF32P + k4);
                uint32_t h0 = pack_f16(v.y, v.x);
                uint32_t h1 = pack_f16(v.w, v.z);
                *(uint2*)(A16 + row * A16RP + (k4 >> 1)) = make_uint2(h0, h1);
            }
            const float* Bf = smf + BF32_OFF + buf * BSZ32;
            uint32_t* B16 = smu + B16_OFF + buf * B16SZ;
#pragma unroll
            for (int i = 0; i < 4; i++) {
                int g = tid + i * 256;
                int row = g >> 5;
                int n4 = (g & 31) * 4;
                float4 v = *(const float4*)(Bf + row * BF32P + n4);
                uint32_t h0 = pack_f16(v.y, v.x);
                uint32_t h1 = pack_f16(v.w, v.z);
                *(uint2*)(B16 + row * B16RP + (n4 >> 1)) = make_uint2(h0, h1);
            }
        }
        __syncthreads();

        // fp32 stage `buf` is now free: prefetch chunk ch+2 into it
        if (ch + 2 < nch) load_stage(ch + 2, buf);

        // ---- mma on fp16 stage ----
        const uint32_t a_base = sm_b + (uint32_t)((A16_OFF + buf * A16SZ) * 4);
        const uint32_t b_base = sm_b + (uint32_t)((B16_OFF + buf * B16SZ) * 4);
#pragma unroll
        for (int kk = 0; kk < 2; kk++) {
            uint32_t af[4][4];
#pragma unroll
            for (int mt = 0; mt < 4; mt++) {
                uint32_t addr = a_base
                    + (uint32_t)((wm + mt * 16 + a_mloc) * 80)
                    + (uint32_t)(kk * 32 + a_koffB);
                ldsm_x4(af[mt], addr);
            }
            uint32_t bf[2][4];
#pragma unroll
            for (int nt16 = 0; nt16 < 2; nt16++) {
                uint32_t addr = b_base
                    + (uint32_t)((kk * 16 + b_kloc) * 272)
                    + (uint32_t)((wn + nt16 * 16 + b_nloc) * 2);
                ldsm_x4_t(bf[nt16], addr);
            }
#pragma unroll
            for (int mt = 0; mt < 4; mt++) {
#pragma unroll
                for (int nt16 = 0; nt16 < 2; nt16++) {
                    mma_f16(acc[mt][nt16 * 2 + 0], af[mt], &bf[nt16][0]);
                    mma_f16(acc[mt][nt16 * 2 + 1], af[mt], &bf[nt16][2]);
                }
            }
        }
        __syncthreads();
    }

    // Epilogue: bias + store
#pragma unroll
    for (int mt = 0; mt < 4; mt++) {
#pragma unroll
        for (int nt = 0; nt < 4; nt++) {
            int row = row0 + wm + mt * 16 + r;
            int col = col0 + wn + nt * 8 + c * 2;
            float2 bv = *(const float2*)(bias + col);
            float2 o0, o1;
            o0.x = acc[mt][nt][0] + bv.x;
            o0.y = acc[mt][nt][1] + bv.y;
            o1.x = acc[mt][nt][2] + bv.x;
            o1.y = acc[mt][nt][3] + bv.y;
            *(float2*)(C + (size_t)row * N + col) = o0;
            *(float2*)(C + (size_t)(row + 8) * N + col) = o1;
        }
    }
}

// ===========================================================================
// Attention with tf32 mma (unchanged from R5 pass).
// ===========================================================================
#define QS_PAD 68
#define VS_PAD 72
#define ATT_QS  (64 * QS_PAD)
#define ATT_KS  (64 * QS_PAD)
#define ATT_VS  (64 * VS_PAD)
#define ATT_PS  (64 * QS_PAD)
#define ATT_SMEM ((ATT_QS + ATT_KS + ATT_VS + ATT_PS) * 4)

__global__ __launch_bounds__(128)
void attn_mma_kernel(const float* __restrict__ qkv,
                     const float* __restrict__ pqkv,
                     float* __restrict__ y) {
    extern __shared__ uint32_t smu[];
    uint32_t* Qs = smu;
    uint32_t* Ks = smu + ATT_QS;
    uint32_t* Vs = smu + ATT_QS + ATT_KS;
    uint32_t* Ps = smu + ATT_QS + ATT_KS + ATT_VS;

    const int bh = blockIdx.x;
    const int b = bh / NHEAD;
    const int h = bh % NHEAD;
    const int qt = blockIdx.y;
    const int tid = threadIdx.x;
    const int w = tid >> 5;
    const int lane = tid & 31;
    const int r = lane >> 2;
    const int c = lane & 3;
    const float scale = 0.125f;

    const float* qbase = qkv + (size_t)(b * SEQ_T + qt * 64) * C3 + h * HDIM;
#pragma unroll
    for (int i = 0; i < 8; i++) {
        int idx = tid + i * 128;
        int row = idx >> 4;
        int c4 = (idx & 15) * 4;
        float4 v = *(const float4*)(qbase + (size_t)row * C3 + c4);
        uint4 t = make_uint4(f2tf32(v.x), f2tf32(v.y), f2tf32(v.z), f2tf32(v.w));
        *(uint4*)&Qs[row * QS_PAD + c4] = t;
    }

    float out[8][4];
#pragma unroll
    for (int nt = 0; nt < 8; nt++)
#pragma unroll
        for (int j = 0; j < 4; j++) out[nt][j] = 0.0f;

    const int gr0 = qt * 64 + w * 16 + r;
    const int gr1 = gr0 + 8;

    for (int pass = 0; pass < 2; pass++) {
        const int ntiles = (pass == 0) ? (qt + 1) : 1;
        const float* src = (pass == 0) ? qkv : pqkv;
        const int rowbase = (pass == 0) ? (b * SEQ_T) : (b * SEQ_TP);

        float m0 = -1e30f, m1 = -1e30f, l0 = 0.0f, l1 = 0.0f;
        float o[8][4];
#pragma unroll
        for (int nt = 0; nt < 8; nt++)
#pragma unroll
            for (int j = 0; j < 4; j++) o[nt][j] = 0.0f;

        for (int kt = 0; kt < ntiles; kt++) {
            __syncthreads();
            const float* kb = src + (size_t)(rowbase + kt * 64) * C3 + CH + h * HDIM;
            const float* vb = kb + CH;
#pragma unroll
            for (int i = 0; i < 8; i++) {
                int idx = tid + i * 128;
                int row = idx >> 4;
                int c4 = (idx & 15) * 4;
                float4 v = *(const float4*)(kb + (size_t)row * C3 + c4);
                uint4 t = make_uint4(f2tf32(v.x), f2tf32(v.y), f2tf32(v.z), f2tf32(v.w));
                *(uint4*)&Ks[row * QS_PAD + c4] = t;
                float4 u = *(const float4*)(vb + (size_t)row * C3 + c4);
                uint4 s = make_uint4(f2tf32(u.x), f2tf32(u.y), f2tf32(u.z), f2tf32(u.w));
                *(uint4*)&Vs[row * VS_PAD + c4] = s;
            }
            __syncthreads();

            float s[8][4];
#pragma unroll
            for (int nt = 0; nt < 8; nt++)
#pragma unroll
                for (int j = 0; j < 4; j++) s[nt][j] = 0.0f;
#pragma unroll
            for (int ks = 0; ks < 8; ks++) {
                const int kbb = ks * 8;
                uint32_t aq[4];
                int rowA = w * 16 + r;
                aq[0] = Qs[rowA * QS_PAD + kbb + c];
                aq[1] = Qs[(rowA + 8) * QS_PAD + kbb + c];
                aq[2] = Qs[rowA * QS_PAD + kbb + c + 4];
                aq[3] = Qs[(rowA + 8) * QS_PAD + kbb + c + 4];
#pragma unroll
                for (int nt = 0; nt < 8; nt++) {
                    uint32_t bk[2];
                    bk[0] = Ks[(nt * 8 + r) * QS_PAD + kbb + c];
                    bk[1] = Ks[(nt * 8 + r) * QS_PAD + kbb + c + 4];
                    mma_tf32(s[nt], aq, bk);
                }
            }

            const int cbase = (pass == 0) ? kt * 64 : 0;
#pragma unroll
            for (int nt = 0; nt < 8; nt++) {
                int gc = cbase + nt * 8 + 2 * c;
                s[nt][0] = (gc     > gr0) ? -1e30f : s[nt][0] * scale;
                s[nt][1] = (gc + 1 > gr0) ? -1e30f : s[nt][1] * scale;
                s[nt][2] = (gc     > gr1) ? -1e30f : s[nt][2] * scale;
                s[nt][3] = (gc + 1 > gr1) ? -1e30f : s[nt][3] * scale;
            }

            float mx0 = -1e30f, mx1 = -1e30f;
#pragma unroll
            for (int nt = 0; nt < 8; nt++) {
                mx0 = fmaxf(mx0, fmaxf(s[nt][0], s[nt][1]));
                mx1 = fmaxf(mx1, fmaxf(s[nt][2], s[nt][3]));
            }
            mx0 = fmaxf(mx0, __shfl_xor_sync(0xffffffffu, mx0, 1));
            mx0 = fmaxf(mx0, __shfl_xor_sync(0xffffffffu, mx0, 2));
            mx1 = fmaxf(mx1, __shfl_xor_sync(0xffffffffu, mx1, 1));
            mx1 = fmaxf(mx1, __shfl_xor_sync(0xffffffffu, mx1, 2));

            float mn0 = fmaxf(m0, mx0);
            float mn1 = fmaxf(m1, mx1);
            float a0 = __expf(m0 - mn0);
            float a1 = __expf(m1 - mn1);
            m0 = mn0; m1 = mn1;

            float rs0 = 0.0f, rs1 = 0.0f;
#pragma unroll
            for (int nt = 0; nt < 8; nt++) {
                s[nt][0] = __expf(s[nt][0] - mn0);
                s[nt][1] = __expf(s[nt][1] - mn0);
                s[nt][2] = __expf(s[nt][2] - mn1);
                s[nt][3] = __expf(s[nt][3] - mn1);
                rs0 += s[nt][0] + s[nt][1];
                rs1 += s[nt][2] + s[nt][3];
            }
            rs0 += __shfl_xor_sync(0xffffffffu, rs0, 1);
            rs0 += __shfl_xor_sync(0xffffffffu, rs0, 2);
            rs1 += __shfl_xor_sync(0xffffffffu, rs1, 1);
            rs1 += __shfl_xor_sync(0xffffffffu, rs1, 2);
            l0 = l0 * a0 + rs0;
            l1 = l1 * a1 + rs1;
#pragma unroll
            for (int nt = 0; nt < 8; nt++) {
                o[nt][0] *= a0; o[nt][1] *= a0;
                o[nt][2] *= a1; o[nt][3] *= a1;
            }

            {
                int rowA = w * 16 + r;
#pragma unroll
                for (int nt = 0; nt < 8; nt++) {
                    uint2 p0 = make_uint2(f2tf32(s[nt][0]), f2tf32(s[nt][1]));
                    uint2 p1 = make_uint2(f2tf32(s[nt][2]), f2tf32(s[nt][3]));
                    *(uint2*)&Ps[rowA * QS_PAD + nt * 8 + 2 * c] = p0;
                    *(uint2*)&Ps[(rowA + 8) * QS_PAD + nt * 8 + 2 * c] = p1;
                }
            }
            __syncwarp();

#pragma unroll
            for (int ks = 0; ks < 8; ks++) {
                const int kbb = ks * 8;
                uint32_t ap[4];
                int rowA = w * 16 + r;
                ap[0] = Ps[rowA * QS_PAD + kbb + c];
                ap[1] = Ps[(rowA + 8) * QS_PAD + kbb + c];
                ap[2] = Ps[rowA * QS_PAD + kbb + c + 4];
                ap[3] = Ps[(rowA + 8) * QS_PAD + kbb + c + 4];
#pragma unroll
                for (int nt = 0; nt < 8; nt++) {
                    uint32_t bv[2];
                    bv[0] = Vs[(kbb + c) * VS_PAD + nt * 8 + r];
                    bv[1] = Vs[(kbb + c + 4) * VS_PAD + nt * 8 + r];
                    mma_tf32(o[nt], ap, bv);
                }
            }
        }

        float inv0 = 1.0f / l0;
        float inv1 = 1.0f / l1;
#pragma unroll
        for (int nt = 0; nt < 8; nt++) {
            out[nt][0] += o[nt][0] * inv0;
            out[nt][1] += o[nt][1] * inv0;
            out[nt][2] += o[nt][2] * inv1;
            out[nt][3] += o[nt][3] * inv1;
        }
    }

    {
        float* y0 = y + (size_t)(b * SEQ_T + gr0) * CH + h * HDIM;
        float* y1 = y + (size_t)(b * SEQ_T + gr1) * CH + h * HDIM;
#pragma unroll
        for (int nt = 0; nt < 8; nt++) {
            int col = nt * 8 + 2 * c;
            *(float2*)(y0 + col) = make_float2(out[nt][0], out[nt][1]);
            *(float2*)(y1 + col) = make_float2(out[nt][2], out[nt][3]);
        }
    }
}

// ---------------------------------------------------------------------------
// Launch
// ---------------------------------------------------------------------------
extern "C" void kernel_launch(void* const* d_in, const int* in_sizes, int n_in,
                              void* d_out, int out_size) {
    const float* x        = (const float*)d_in[0];
    const float* prefix   = (const float*)d_in[1];
    const float* w_attn   = (const float*)d_in[2];
    const float* b_attn   = (const float*)d_in[3];
    const float* w_prefix = (const float*)d_in[4];
    const float* b_prefix = (const float*)d_in[5];
    const float* w_proj   = (const float*)d_in[6];
    const float* b_proj   = (const float*)d_in[7];
    float* out = (float*)d_out;

    float *qkv_ptr, *pqkv_ptr, *y_ptr;
    cudaGetSymbolAddress((void**)&qkv_ptr, g_qkv);
    cudaGetSymbolAddress((void**)&pqkv_ptr, g_pqkv);
    cudaGetSymbolAddress((void**)&y_ptr, g_y);

    cudaFuncSetAttribute(gemm_f16_kernel, cudaFuncAttributeMaxDynamicSharedMemorySize, GEMM_SMEM);
    cudaFuncSetAttribute(attn_mma_kernel, cudaFuncAttributeMaxDynamicSharedMemorySize, ATT_SMEM);

    // 1) qkv = x @ w_attn + b_attn
    {
        dim3 grid(C3 / 128, (BATCH * SEQ_T) / 128);
        gemm_f16_kernel<<<grid, 256, GEMM_SMEM>>>(x, w_attn, b_attn, qkv_ptr,
                                                  BATCH * SEQ_T, C3, CH);
    }
    // 2) pqkv = prefix @ w_prefix + b_prefix
    {
        dim3 grid(C3 / 128, (BATCH * SEQ_TP) / 128);
        gemm_f16_kernel<<<grid, 256, GEMM_SMEM>>>(prefix, w_prefix, b_prefix, pqkv_ptr,
                                                  BATCH * SEQ_TP, C3, CH);
    }
    // 3) attention -> y
    {
        dim3 grid(BATCH * NHEAD, SEQ_T / 64);
        attn_mma_kernel<<<grid, 128, ATT_SMEM>>>(qkv_ptr, pqkv_ptr, y_ptr);
    }
    // 4) out = y @ w_proj + b_proj
    {
        dim3 grid(CH / 128, (BATCH * SEQ_T) / 128);
        gemm_f16_kernel<<<grid, 256, GEMM_SMEM>>>(y_ptr, w_proj, b_proj, out,
                                                  BATCH * SEQ_T, CH, CH);
    }
}

// round 7
// speedup vs baseline: 6.0058x; 1.6274x over previous
#include <cuda_runtime.h>
#include <cuda_fp16.h>
#include <math.h>
#include <stdint.h>

// Problem constants
#define BATCH 8
#define SEQ_T 1024
#define SEQ_TP 64
#define CH 1024
#define NHEAD 16
#define HDIM 64
#define C3 (3 * CH)

// Scratch (device globals: allocation-free rule)
__device__ __half g_x16[BATCH * SEQ_T * CH];
__device__ __half g_prefix16[BATCH * SEQ_TP * CH];
__device__ __half g_wattn16[CH * C3];
__device__ __half g_wprefix16[CH * C3];
__device__ __half g_wproj16[CH * CH];
__device__ __half g_qkv16[BATCH * SEQ_T * C3];
__device__ __half g_pqkv16[BATCH * SEQ_TP * C3];
__device__ __half g_y16[BATCH * SEQ_T * CH];

// ===========================================================================
// helpers (compute_80+ features only)
// ===========================================================================
__device__ __forceinline__ void mma_f16(float* d, const uint32_t* a, const uint32_t* b) {
    asm volatile(
        "mma.sync.aligned.m16n8k16.row.col.f32.f16.f16.f32 "
        "{%0,%1,%2,%3}, {%4,%5,%6,%7}, {%8,%9}, {%0,%1,%2,%3};"
        : "+f"(d[0]), "+f"(d[1]), "+f"(d[2]), "+f"(d[3])
        : "r"(a[0]), "r"(a[1]), "r"(a[2]), "r"(a[3]), "r"(b[0]), "r"(b[1]));
}

__device__ __forceinline__ void ldsm_x4(uint32_t* r, uint32_t addr) {
    asm volatile(
        "ldmatrix.sync.aligned.m8n8.x4.shared.b16 {%0,%1,%2,%3}, [%4];"
        : "=r"(r[0]), "=r"(r[1]), "=r"(r[2]), "=r"(r[3]) : "r"(addr));
}

__device__ __forceinline__ void ldsm_x4_t(uint32_t* r, uint32_t addr) {
    asm volatile(
        "ldmatrix.sync.aligned.m8n8.x4.trans.shared.b16 {%0,%1,%2,%3}, [%4];"
        : "=r"(r[0]), "=r"(r[1]), "=r"(r[2]), "=r"(r[3]) : "r"(addr));
}

// pack {hi, lo} -> f16x2 (lo in lower half)
__device__ __forceinline__ uint32_t pack_f16(float hi, float lo) {
    uint32_t h;
    asm("cvt.rn.f16x2.f32 %0, %1, %2;" : "=r"(h) : "f"(hi), "f"(lo));
    return h;
}

__device__ __forceinline__ uint32_t smem_u32(const void* p) {
    uint32_t a;
    asm("{ .reg .u64 t; cvta.to.shared.u64 t, %1; cvt.u32.u64 %0, t; }"
        : "=r"(a) : "l"(p));
    return a;
}

__device__ __forceinline__ void cp16(uint32_t dst, const void* src) {
    asm volatile("cp.async.cg.shared.global [%0], [%1], 16;" :: "r"(dst), "l"(src));
}
#define CP_COMMIT() asm volatile("cp.async.commit_group;" ::: "memory")
#define CP_WAIT(n)  asm volatile("cp.async.wait_group %0;" :: "n"(n) : "memory")

// ===========================================================================
// fp32 -> fp16 conversion (n multiple of 4)
// ===========================================================================
__global__ void cvt_f32_f16(const float* __restrict__ in, uint32_t* __restrict__ out, int n4) {
    int i = blockIdx.x * blockDim.x + threadIdx.x;
    if (i < n4) {
        float4 v = ((const float4*)in)[i];
        uint2 o;
        o.x = pack_f16(v.y, v.x);
        o.y = pack_f16(v.w, v.z);
        *(uint2*)&out[2 * i] = o;
    }
}

// ===========================================================================
// fp16 tensor-core GEMM: C = A[M,K] @ B[K,N] + bias.  A,B fp16 row-major.
// Block 128x128, BK=32, 256 thr (8 warps 2x4, warp tile 64x32).
// 3-stage cp.async ring directly in fp16; ldmatrix + mma.m16n8k16.
// A smem: [128 rows][40 halfs] (80 B/row). B smem: [32 k][136 halfs] (272 B).
// ===========================================================================
#define A_STG 10240                      // bytes per A stage (128*80)
#define B_STG 8704                       // bytes per B stage (32*272)
#define B_OFF (3 * A_STG)                // 30720
#define GEMM_SMEM (B_OFF + 3 * B_STG)    // 56832 bytes

template <bool OUT_HALF>
__global__ __launch_bounds__(256)
void gemm_f16_kernel(const __half* __restrict__ A,
                     const __half* __restrict__ B,
                     const float* __restrict__ bias,
                     float* __restrict__ Cf,
                     __half* __restrict__ Ch,
                     int M, int N, int K) {
    extern __shared__ char smc[];
    const uint32_t sm_b = smem_u32(smc);

    const int tid = threadIdx.x;
    const int wid = tid >> 5;
    const int lane = tid & 31;
    const int r = lane >> 2;
    const int c = lane & 3;
    const int wm = (wid >> 2) * 64;
    const int wn = (wid & 3) * 32;
    const int row0 = blockIdx.y * 128;
    const int col0 = blockIdx.x * 128;

    const int mat = lane >> 3;
    const int m8r = lane & 7;
    const int a_mloc = (mat & 1) * 8 + m8r;   // row within 16
    const int a_koffB = (mat >> 1) * 16;      // byte offset within 32-half k
    const int b_kloc = (mat & 1) * 8 + m8r;
    const int b_nloc = (mat >> 1) * 8;

    float acc[4][4][4];
#pragma unroll
    for (int mt = 0; mt < 4; mt++)
#pragma unroll
        for (int nt = 0; nt < 4; nt++)
#pragma unroll
            for (int j = 0; j < 4; j++) acc[mt][nt][j] = 0.0f;

    const int nch = K >> 5;

    auto load_stage = [&](int ch, int st) {
#pragma unroll
        for (int i = 0; i < 2; i++) {
            int idx = tid + i * 256;          // 0..511
            int rw = idx >> 2;                // 0..127
            int ck = idx & 3;                 // 16B chunk
            uint32_t dst = sm_b + (uint32_t)(st * A_STG + rw * 80 + ck * 16);
            cp16(dst, A + (size_t)(row0 + rw) * K + ch * 32 + ck * 8);
        }
#pragma unroll
        for (int i = 0; i < 2; i++) {
            int idx = tid + i * 256;
            int kk = idx >> 4;                // 0..31
            int ck = idx & 15;
            uint32_t dst = sm_b + (uint32_t)(B_OFF + st * B_STG + kk * 272 + ck * 16);
            cp16(dst, B + (size_t)(ch * 32 + kk) * N + col0 + ck * 8);
        }
        CP_COMMIT();
    };

    load_stage(0, 0);
    if (nch > 1) load_stage(1, 1);

    for (int ch = 0; ch < nch; ch++) {
        if (ch + 1 < nch) { CP_WAIT(1); } else { CP_WAIT(0); }
        __syncthreads();
        if (ch + 2 < nch) load_stage(ch + 2, (ch + 2) % 3);

        const int buf = ch % 3;
        const uint32_t a_base = sm_b + (uint32_t)(buf * A_STG);
        const uint32_t b_base = sm_b + (uint32_t)(B_OFF + buf * B_STG);
#pragma unroll
        for (int kk = 0; kk < 2; kk++) {
            uint32_t af[4][4];
#pragma unroll
            for (int mt = 0; mt < 4; mt++) {
                uint32_t addr = a_base
                    + (uint32_t)((wm + mt * 16 + a_mloc) * 80)
                    + (uint32_t)(kk * 32 + a_koffB);
                ldsm_x4(af[mt], addr);
            }
            uint32_t bf[2][4];
#pragma unroll
            for (int nt16 = 0; nt16 < 2; nt16++) {
                uint32_t addr = b_base
                    + (uint32_t)((kk * 16 + b_kloc) * 272)
                    + (uint32_t)((wn + nt16 * 16 + b_nloc) * 2);
                ldsm_x4_t(bf[nt16], addr);
            }
#pragma unroll
            for (int mt = 0; mt < 4; mt++) {
#pragma unroll
                for (int nt16 = 0; nt16 < 2; nt16++) {
                    mma_f16(acc[mt][nt16 * 2 + 0], af[mt], &bf[nt16][0]);
                    mma_f16(acc[mt][nt16 * 2 + 1], af[mt], &bf[nt16][2]);
                }
            }
        }
        __syncthreads();
    }

    // Epilogue: bias + store
#pragma unroll
    for (int mt = 0; mt < 4; mt++) {
#pragma unroll
        for (int nt = 0; nt < 4; nt++) {
            int row = row0 + wm + mt * 16 + r;
            int col = col0 + wn + nt * 8 + c * 2;
            float2 bv = *(const float2*)(bias + col);
            float v00 = acc[mt][nt][0] + bv.x;
            float v01 = acc[mt][nt][1] + bv.y;
            float v10 = acc[mt][nt][2] + bv.x;
            float v11 = acc[mt][nt][3] + bv.y;
            if (OUT_HALF) {
                *(uint32_t*)&Ch[(size_t)row * N + col] = pack_f16(v01, v00);
                *(uint32_t*)&Ch[(size_t)(row + 8) * N + col] = pack_f16(v11, v10);
            } else {
                *(float2*)(Cf + (size_t)row * N + col) = make_float2(v00, v01);
                *(float2*)(Cf + (size_t)(row + 8) * N + col) = make_float2(v10, v11);
            }
        }
    }
}

// ===========================================================================
// fp16 attention (FA2-style): Grid (B*H, T/64), 128 threads (4 warps).
// Q/K/V fp16 in smem [64][72] halfs; S & O via mma.m16n8k16;
// P converted to A-fragments in registers (no smem round trip).
// ===========================================================================
#define ATT_PAD 72   // halfs per row (144 B)

__global__ __launch_bounds__(128)
void attn_f16_kernel(const __half* __restrict__ qkv,
                     const __half* __restrict__ pqkv,
                     __half* __restrict__ y) {
    __shared__ __half Qs[64 * ATT_PAD];
    __shared__ __half Ks[64 * ATT_PAD];
    __shared__ __half Vs[64 * ATT_PAD];

    const int bh = blockIdx.x;
    const int b = bh / NHEAD;
    const int h = bh % NHEAD;
    const int qt = blockIdx.y;
    const int tid = threadIdx.x;
    const int w = tid >> 5;
    const int lane = tid & 31;
    const int r = lane >> 2;
    const int c = lane & 3;
    const float scale = 0.125f;

    const int mat = lane >> 3;
    const int m8r = lane & 7;
    const int mloc = (mat & 1) * 8 + m8r;
    const int koffB = (mat >> 1) * 16;

    const uint32_t qaddr = smem_u32(Qs);
    const uint32_t kaddr = smem_u32(Ks);
    const uint32_t vaddr = smem_u32(Vs);

    // Load Q tile (64 rows x 64 halfs)
    const __half* qbase = qkv + (size_t)(b * SEQ_T + qt * 64) * C3 + h * HDIM;
#pragma unroll
    for (int i = 0; i < 4; i++) {
        int idx = tid + i * 128;
        int row = idx >> 3;
        int c8 = (idx & 7) * 8;
        *(uint4*)&Qs[row * ATT_PAD + c8] = *(const uint4*)(qbase + (size_t)row * C3 + c8);
    }
    __syncthreads();

    // Q fragments (constant across kv tiles)
    uint32_t aq[4][4];
#pragma unroll
    for (int ks = 0; ks < 4; ks++) {
        uint32_t addr = qaddr + (uint32_t)((w * 16 + mloc) * 144) + (uint32_t)(ks * 32 + koffB);
        ldsm_x4(aq[ks], addr);
    }

    float out[8][4];
#pragma unroll
    for (int nt = 0; nt < 8; nt++)
#pragma unroll
        for (int j = 0; j < 4; j++) out[nt][j] = 0.0f;

    const int gr0 = qt * 64 + w * 16 + r;
    const int gr1 = gr0 + 8;

    for (int pass = 0; pass < 2; pass++) {
        const int ntiles = (pass == 0) ? (qt + 1) : 1;
        const __half* src = (pass == 0) ? qkv : pqkv;
        const int rowbase = (pass == 0) ? (b * SEQ_T) : (b * SEQ_TP);

        float m0 = -1e30f, m1 = -1e30f, l0 = 0.0f, l1 = 0.0f;
        float o[8][4];
#pragma unroll
        for (int nt = 0; nt < 8; nt++)
#pragma unroll
            for (int j = 0; j < 4; j++) o[nt][j] = 0.0f;

        for (int kt = 0; kt < ntiles; kt++) {
            __syncthreads();
            const __half* kb = src + (size_t)(rowbase + kt * 64) * C3 + CH + h * HDIM;
            const __half* vb = kb + CH;
#pragma unroll
            for (int i = 0; i < 4; i++) {
                int idx = tid + i * 128;
                int row = idx >> 3;
                int c8 = (idx & 7) * 8;
                *(uint4*)&Ks[row * ATT_PAD + c8] = *(const uint4*)(kb + (size_t)row * C3 + c8);
                *(uint4*)&Vs[row * ATT_PAD + c8] = *(const uint4*)(vb + (size_t)row * C3 + c8);
            }
            __syncthreads();

            // S = Q K^T
            float s[8][4];
#pragma unroll
            for (int nt = 0; nt < 8; nt++)
#pragma unroll
                for (int j = 0; j < 4; j++) s[nt][j] = 0.0f;
#pragma unroll
            for (int ks = 0; ks < 4; ks++) {
#pragma unroll
                for (int nt16 = 0; nt16 < 4; nt16++) {
                    uint32_t bk[4];
                    uint32_t addr = kaddr + (uint32_t)((nt16 * 16 + mloc) * 144)
                                  + (uint32_t)(ks * 32 + koffB);
                    ldsm_x4(bk, addr);
                    uint32_t b0[2] = { bk[0], bk[2] };
                    uint32_t b1[2] = { bk[1], bk[3] };
                    mma_f16(s[nt16 * 2 + 0], aq[ks], b0);
                    mma_f16(s[nt16 * 2 + 1], aq[ks], b1);
                }
            }

            // scale + causal mask
            const int cbase = (pass == 0) ? kt * 64 : 0;
#pragma unroll
            for (int nt = 0; nt < 8; nt++) {
                int gc = cbase + nt * 8 + 2 * c;
                s[nt][0] = (gc     > gr0) ? -1e30f : s[nt][0] * scale;
                s[nt][1] = (gc + 1 > gr0) ? -1e30f : s[nt][1] * scale;
                s[nt][2] = (gc     > gr1) ? -1e30f : s[nt][2] * scale;
                s[nt][3] = (gc + 1 > gr1) ? -1e30f : s[nt][3] * scale;
            }

            // online softmax
            float mx0 = -1e30f, mx1 = -1e30f;
#pragma unroll
            for (int nt = 0; nt < 8; nt++) {
                mx0 = fmaxf(mx0, fmaxf(s[nt][0], s[nt][1]));
                mx1 = fmaxf(mx1, fmaxf(s[nt][2], s[nt][3]));
            }
            mx0 = fmaxf(mx0, __shfl_xor_sync(0xffffffffu, mx0, 1));
            mx0 = fmaxf(mx0, __shfl_xor_sync(0xffffffffu, mx0, 2));
            mx1 = fmaxf(mx1, __shfl_xor_sync(0xffffffffu, mx1, 1));
            mx1 = fmaxf(mx1, __shfl_xor_sync(0xffffffffu, mx1, 2));

            float mn0 = fmaxf(m0, mx0);
            float mn1 = fmaxf(m1, mx1);
            float a0 = __expf(m0 - mn0);
            float a1 = __expf(m1 - mn1);
            m0 = mn0; m1 = mn1;

            float rs0 = 0.0f, rs1 = 0.0f;
#pragma unroll
            for (int nt = 0; nt < 8; nt++) {
                s[nt][0] = __expf(s[nt][0] - mn0);
                s[nt][1] = __expf(s[nt][1] - mn0);
                s[nt][2] = __expf(s[nt][2] - mn1);
                s[nt][3] = __expf(s[nt][3] - mn1);
                rs0 += s[nt][0] + s[nt][1];
                rs1 += s[nt][2] + s[nt][3];
            }
            rs0 += __shfl_xor_sync(0xffffffffu, rs0, 1);
            rs0 += __shfl_xor_sync(0xffffffffu, rs0, 2);
            rs1 += __shfl_xor_sync(0xffffffffu, rs1, 1);
            rs1 += __shfl_xor_sync(0xffffffffu, rs1, 2);
            l0 = l0 * a0 + rs0;
            l1 = l1 * a1 + rs1;
#pragma unroll
            for (int nt = 0; nt < 8; nt++) {
                o[nt][0] *= a0; o[nt][1] *= a0;
                o[nt][2] *= a1; o[nt][3] *= a1;
            }

            // O += P V  (P fragments built in registers from accumulator layout)
#pragma unroll
            for (int kk = 0; kk < 4; kk++) {
                uint32_t ap[4];
                ap[0] = pack_f16(s[2 * kk][1],     s[2 * kk][0]);
                ap[1] = pack_f16(s[2 * kk][3],     s[2 * kk][2]);
                ap[2] = pack_f16(s[2 * kk + 1][1], s[2 * kk + 1][0]);
                ap[3] = pack_f16(s[2 * kk + 1][3], s[2 * kk + 1][2]);
#pragma unroll
                for (int nt16 = 0; nt16 < 4; nt16++) {
                    uint32_t bv[4];
                    uint32_t addr = vaddr + (uint32_t)((kk * 16 + mloc) * 144)
                                  + (uint32_t)(nt16 * 32 + koffB);
                    ldsm_x4_t(bv, addr);
                    mma_f16(o[nt16 * 2 + 0], ap, &bv[0]);
                    mma_f16(o[nt16 * 2 + 1], ap, &bv[2]);
                }
            }
        }

        // normalize & accumulate
        float inv0 = 1.0f / l0;
        float inv1 = 1.0f / l1;
#pragma unroll
        for (int nt = 0; nt < 8; nt++) {
            out[nt][0] += o[nt][0] * inv0;
            out[nt][1] += o[nt][1] * inv0;
            out[nt][2] += o[nt][2] * inv1;
            out[nt][3] += o[nt][3] * inv1;
        }
    }

    // Write y (fp16)
    {
        __half* y0 = y + (size_t)(b * SEQ_T + gr0) * CH + h * HDIM;
        __half* y1 = y + (size_t)(b * SEQ_T + gr1) * CH + h * HDIM;
#pragma unroll
        for (int nt = 0; nt < 8; nt++) {
            int col = nt * 8 + 2 * c;
            *(uint32_t*)&y0[col] = pack_f16(out[nt][1], out[nt][0]);
            *(uint32_t*)&y1[col] = pack_f16(out[nt][3], out[nt][2]);
        }
    }
}

// ---------------------------------------------------------------------------
// Launch
// ---------------------------------------------------------------------------
extern "C" void kernel_launch(void* const* d_in, const int* in_sizes, int n_in,
                              void* d_out, int out_size) {
    const float* x        = (const float*)d_in[0];
    const float* prefix   = (const float*)d_in[1];
    const float* w_attn   = (const float*)d_in[2];
    const float* b_attn   = (const float*)d_in[3];
    const float* w_prefix = (const float*)d_in[4];
    const float* b_prefix = (const float*)d_in[5];
    const float* w_proj   = (const float*)d_in[6];
    const float* b_proj   = (const float*)d_in[7];
    float* out = (float*)d_out;

    __half *x16, *p16, *wa16, *wp16, *wo16, *qkv16, *pqkv16, *y16;
    cudaGetSymbolAddress((void**)&x16, g_x16);
    cudaGetSymbolAddress((void**)&p16, g_prefix16);
    cudaGetSymbolAddress((void**)&wa16, g_wattn16);
    cudaGetSymbolAddress((void**)&wp16, g_wprefix16);
    cudaGetSymbolAddress((void**)&wo16, g_wproj16);
    cudaGetSymbolAddress((void**)&qkv16, g_qkv16);
    cudaGetSymbolAddress((void**)&pqkv16, g_pqkv16);
    cudaGetSymbolAddress((void**)&y16, g_y16);

    cudaFuncSetAttribute(gemm_f16_kernel<true>, cudaFuncAttributeMaxDynamicSharedMemorySize, GEMM_SMEM);
    cudaFuncSetAttribute(gemm_f16_kernel<false>, cudaFuncAttributeMaxDynamicSharedMemorySize, GEMM_SMEM);

    // 0) fp32 -> fp16 conversions
    {
        int n;
        n = BATCH * SEQ_T * CH / 4;
        cvt_f32_f16<<<(n + 255) / 256, 256>>>(x, (uint32_t*)x16, n);
        n = BATCH * SEQ_TP * CH / 4;
        cvt_f32_f16<<<(n + 255) / 256, 256>>>(prefix, (uint32_t*)p16, n);
        n = CH * C3 / 4;
        cvt_f32_f16<<<(n + 255) / 256, 256>>>(w_attn, (uint32_t*)wa16, n);
        cvt_f32_f16<<<(n + 255) / 256, 256>>>(w_prefix, (uint32_t*)wp16, n);
        n = CH * CH / 4;
        cvt_f32_f16<<<(n + 255) / 256, 256>>>(w_proj, (uint32_t*)wo16, n);
    }
    // 1) qkv16 = x16 @ wattn16 + b_attn (fp16 out)
    {
        dim3 grid(C3 / 128, (BATCH * SEQ_T) / 128);
        gemm_f16_kernel<true><<<grid, 256, GEMM_SMEM>>>(x16, wa16, b_attn, nullptr, qkv16,
                                                        BATCH * SEQ_T, C3, CH);
    }
    // 2) pqkv16 = prefix16 @ wprefix16 + b_prefix (fp16 out)
    {
        dim3 grid(C3 / 128, (BATCH * SEQ_TP) / 128);
        gemm_f16_kernel<true><<<grid, 256, GEMM_SMEM>>>(p16, wp16, b_prefix, nullptr, pqkv16,
                                                        BATCH * SEQ_TP, C3, CH);
    }
    // 3) attention -> y16 (fp16)
    {
        dim3 grid(BATCH * NHEAD, SEQ_T / 64);
        attn_f16_kernel<<<grid, 128>>>(qkv16, pqkv16, y16);
    }
    // 4) out = y16 @ wproj16 + b_proj (fp32 out)
    {
        dim3 grid(CH / 128, (BATCH * SEQ_T) / 128);
        gemm_f16_kernel<false><<<grid, 256, GEMM_SMEM>>>(y16, wo16, b_proj, out, nullptr,
                                                         BATCH * SEQ_T, CH, CH);
    }
}